// round 15
// baseline (speedup 1.0000x reference)
#include <cuda_runtime.h>
#include <cuda_fp16.h>
#include <cstdint>

#define BATCH 16
#define DIM   256
#define NPOS  4096
#define QKVD  768
#define HH    64
#define WW    64
#define EPSF  1e-5f

// ---------------- scratch ----------------
__device__ __half g_xh [(size_t)BATCH * DIM * NPOS];    // fp16 x [b][c][n]
__device__ __half g_qkv[(size_t)BATCH * QKVD * NPOS];   // fp16 [b][768][n]
__device__ __half g_vkT[(size_t)BATCH * DIM * DIM];
__device__ float  g_part[(size_t)BATCH * 8 * DIM * DIM];
__device__ __half g_dw [(size_t)BATCH * DIM * NPOS];
__device__ __half g_y  [(size_t)BATCH * DIM * NPOS];
__device__ float  g_z  [(size_t)BATCH * NPOS];
__device__ float  g_kmean[BATCH * DIM];
__device__ __half g_qw[QKVD * DIM];
__device__ __half g_pw[DIM * DIM];

__device__ __forceinline__ void cp16(uint32_t smem, const void* g) {
    asm volatile("cp.async.cg.shared.global [%0], [%1], 16;" :: "r"(smem), "l"(g));
}
#define CP_COMMIT() asm volatile("cp.async.commit_group;" ::: "memory")
#define CP_WAIT1()  asm volatile("cp.async.wait_group 1;" ::: "memory")
#define CP_WAIT2()  asm volatile("cp.async.wait_group 2;" ::: "memory")

__device__ __forceinline__ void ldsm_x4(uint32_t& r0, uint32_t& r1, uint32_t& r2, uint32_t& r3,
                                        uint32_t addr) {
    asm volatile("ldmatrix.sync.aligned.m8n8.x4.shared.b16 {%0,%1,%2,%3}, [%4];"
                 : "=r"(r0), "=r"(r1), "=r"(r2), "=r"(r3) : "r"(addr));
}
__device__ __forceinline__ void ldsm_x4_t(uint32_t& r0, uint32_t& r1, uint32_t& r2, uint32_t& r3,
                                          uint32_t addr) {
    asm volatile("ldmatrix.sync.aligned.m8n8.x4.trans.shared.b16 {%0,%1,%2,%3}, [%4];"
                 : "=r"(r0), "=r"(r1), "=r"(r2), "=r"(r3) : "r"(addr));
}

#define MMA_F16(acc, a0, a1, a2, a3, b0, b1) \
    asm volatile("mma.sync.aligned.m16n8k16.row.col.f32.f16.f16.f32 " \
                 "{%0,%1,%2,%3}, {%4,%5,%6,%7}, {%8,%9}, {%0,%1,%2,%3};" \
                 : "+f"((acc)[0]), "+f"((acc)[1]), "+f"((acc)[2]), "+f"((acc)[3]) \
                 : "r"(a0), "r"(a1), "r"(a2), "r"(a3), "r"(b0), "r"(b1))

// A-frag lane offset (80B row stride, [rows][k32])
__device__ __forceinline__ uint32_t ldsmA_off(int lane) {
    int row = ((lane >> 3) & 1) * 8 + (lane & 7);
    return (uint32_t)(row * 80 + (lane >> 4) * 16);
}
// B-frag (non-trans, [n][k32], 80B stride)
__device__ __forceinline__ uint32_t ldsmBn_off(int lane) {
    int row = ((lane >> 4) & 1) * 8 + (lane & 7);
    return (uint32_t)(row * 80 + ((lane >> 3) & 1) * 16);
}
// B-frag (trans, [k32][256n], 528B stride)
__device__ __forceinline__ uint32_t ldsmBt_off(int lane) {
    int krow = ((lane >> 3) & 1) * 8 + (lane & 7);
    return (uint32_t)(krow * 528 + ((lane >> 4) & 1) * 16);
}

// ---------------- fp16 mma GEMM: CTA 128m x 256n, warp 64x64, k32 x 4-stage ring ----------------
#define ASTG 10240   // A stage: 128 rows * 80B
#define BSTG 20480   // B stage: 256 rows * 80B (nontrans) or 32 rows * 528B (trans, 16896<=20480)
__global__ __launch_bounds__(256)
void hgemm(const __half* __restrict__ A, const __half* __restrict__ B,
           const float* __restrict__ bias, void* __restrict__ Cv,
           int K, int ldA, int ldB, int ldC,
           long long aStride, long long bStride, long long cStride,
           int kChunks, int biasMode, int bTrans, int outHalf)
{
    extern __shared__ char smc[];

    int z = blockIdx.z;
    int b = z / kChunks, chunk = z - b * kChunks;
    int kStart = chunk * K;
    int m0 = blockIdx.y * 128, n0 = blockIdx.x * 256;
    const __half* Ab = A + (size_t)b * aStride + (size_t)m0 * ldA + kStart;

    int tid = threadIdx.x;
    int lane = tid & 31, wid = tid >> 5;
    int g = lane >> 2, tig = lane & 3;
    int warp_m = (wid & 1) * 64, warp_n = (wid >> 1) * 64;

    uint32_t sbase;
    asm("{ .reg .u64 t; cvta.to.shared.u64 t, %1; cvt.u32.u64 %0, t; }" : "=r"(sbase) : "l"(smc));
    uint32_t sA = sbase, sB = sbase + 4 * ASTG;

    // A loader: 512 16B-chunks (128 rows x 64B), 2 per thread
    int ac0 = tid, ac1 = tid + 256;
    int ar0 = ac0 >> 2, akc0 = ac0 & 3;
    int ar1 = ac1 >> 2, akc1 = ac1 & 3;
    uint32_t aoff0 = (uint32_t)(ar0 * 80 + akc0 * 16);
    uint32_t aoff1 = (uint32_t)(ar1 * 80 + akc1 * 16);
    const __half* ag0 = Ab + (size_t)ar0 * ldA + akc0 * 8;
    const __half* ag1 = Ab + (size_t)ar1 * ldA + akc1 * 8;

    // B loader: 1024 chunks, 4 per thread
    const __half* bgn[4];
    uint32_t boff[4];
    int tkr[4], tnc[4];
    const __half* btg = nullptr;
    if (!bTrans) {
        const __half* Bb = B + (size_t)b * bStride + (size_t)n0 * ldB + kStart;
#pragma unroll
        for (int t = 0; t < 4; ++t) {
            int c = tid + t * 256;
            int br = c >> 2, bkc = c & 3;
            boff[t] = (uint32_t)(br * 80 + bkc * 16);
            bgn[t] = Bb + (size_t)br * ldB + bkc * 8;
        }
    } else {
        btg = B + (size_t)b * bStride + (size_t)kStart * ldB + n0;
#pragma unroll
        for (int t = 0; t < 4; ++t) {
            int c = tid + t * 256;
            tkr[t] = c >> 5; tnc[t] = c & 31;          // 32 rows x 32 chunks (512B/row)
            boff[t] = (uint32_t)(tkr[t] * 528 + tnc[t] * 16);
        }
    }

    uint32_t aF = ldsmA_off(lane) + (uint32_t)warp_m * 80;
    uint32_t bFn = ldsmBn_off(lane) + (uint32_t)warp_n * 80;
    uint32_t bFt = ldsmBt_off(lane) + (uint32_t)warp_n * 2;

    int S = K >> 5;

    float acc[4][8][4];
#pragma unroll
    for (int i = 0; i < 4; ++i)
#pragma unroll
        for (int j = 0; j < 8; ++j)
#pragma unroll
            for (int r = 0; r < 4; ++r) acc[i][j][r] = 0.f;

    // prologue: stages 0..2
#pragma unroll
    for (int ps = 0; ps < 3; ++ps) {
        int kc = ps * 32;
        uint32_t soA = ps * ASTG, soB = ps * BSTG;
        cp16(sA + soA + aoff0, ag0 + kc);
        cp16(sA + soA + aoff1, ag1 + kc);
        if (!bTrans) {
#pragma unroll
            for (int t = 0; t < 4; ++t) cp16(sB + soB + boff[t], bgn[t] + kc);
        } else {
#pragma unroll
            for (int t = 0; t < 4; ++t)
                cp16(sB + soB + boff[t], btg + (size_t)(kc + tkr[t]) * ldB + tnc[t] * 8);
        }
        CP_COMMIT();
    }

    for (int s = 0; s < S; ++s) {
        CP_WAIT2();
        __syncthreads();
        if (s + 3 < S) {
            int bf3 = (s + 3) & 3;
            int kc = (s + 3) * 32;
            uint32_t soA = bf3 * ASTG, soB = bf3 * BSTG;
            cp16(sA + soA + aoff0, ag0 + kc);
            cp16(sA + soA + aoff1, ag1 + kc);
            if (!bTrans) {
#pragma unroll
                for (int t = 0; t < 4; ++t) cp16(sB + soB + boff[t], bgn[t] + kc);
            } else {
#pragma unroll
                for (int t = 0; t < 4; ++t)
                    cp16(sB + soB + boff[t], btg + (size_t)(kc + tkr[t]) * ldB + tnc[t] * 8);
            }
        }
        CP_COMMIT();
        uint32_t stA = sA + (s & 3) * ASTG;
        uint32_t stB = sB + (s & 3) * BSTG;
#pragma unroll
        for (int h = 0; h < 2; ++h) {
            uint32_t af[4][4], bf[8][2];
#pragma unroll
            for (int i = 0; i < 4; ++i)
                ldsm_x4(af[i][0], af[i][1], af[i][2], af[i][3],
                        stA + aF + (uint32_t)(i * 16 * 80 + h * 32));
            if (!bTrans) {
#pragma unroll
                for (int jj = 0; jj < 4; ++jj)
                    ldsm_x4(bf[2 * jj][0], bf[2 * jj][1], bf[2 * jj + 1][0], bf[2 * jj + 1][1],
                            stB + bFn + (uint32_t)(jj * 16 * 80 + h * 32));
            } else {
#pragma unroll
                for (int jj = 0; jj < 4; ++jj)
                    ldsm_x4_t(bf[2 * jj][0], bf[2 * jj][1], bf[2 * jj + 1][0], bf[2 * jj + 1][1],
                              stB + bFt + (uint32_t)(jj * 32 + h * 16 * 528));
            }
#pragma unroll
            for (int i = 0; i < 4; ++i)
#pragma unroll
                for (int j = 0; j < 8; ++j)
                    MMA_F16(acc[i][j], af[i][0], af[i][1], af[i][2], af[i][3], bf[j][0], bf[j][1]);
        }
    }

    // epilogue
#pragma unroll
    for (int i = 0; i < 4; ++i) {
        int row0 = m0 + warp_m + i * 16 + g;
        float br0 = (biasMode == 2) ? bias[row0] : 0.f;
        float br1 = (biasMode == 2) ? bias[row0 + 8] : 0.f;
#pragma unroll
        for (int j = 0; j < 8; ++j) {
            int col = n0 + warp_n + j * 8 + tig * 2;
            if (outHalf) {
                __half* Ch = (__half*)Cv + (size_t)z * cStride;
                *(__half2*)&Ch[(size_t)row0 * ldC + col] =
                    __floats2half2_rn(acc[i][j][0] + br0, acc[i][j][1] + br0);
                *(__half2*)&Ch[(size_t)(row0 + 8) * ldC + col] =
                    __floats2half2_rn(acc[i][j][2] + br1, acc[i][j][3] + br1);
            } else {
                float* Cf = (float*)Cv + (size_t)z * cStride;
                *(float2*)&Cf[(size_t)row0 * ldC + col] =
                    make_float2(acc[i][j][0] + br0, acc[i][j][1] + br0);
                *(float2*)&Cf[(size_t)(row0 + 8) * ldC + col] =
                    make_float2(acc[i][j][2] + br1, acc[i][j][3] + br1);
            }
        }
    }
}

// ---------------- fused attn: y[d][n] = RMSNorm((vkT·q)/z)*nw + dw, fp16. 512 threads ----------------
#define AST2 20480   // 256 rows * 80B
#define BSTT 8704    // 32 k-rows * 272B
#define EPI_BYTES (3 * AST2 + 3 * BSTT)
// B-frag (trans, [k32][128n], 272B stride) for attn_fused
__device__ __forceinline__ uint32_t ldsmBt272_off(int lane) {
    int krow = ((lane >> 3) & 1) * 8 + (lane & 7);
    return (uint32_t)(krow * 272 + ((lane >> 4) & 1) * 16);
}
__global__ __launch_bounds__(512)
void attn_fused(const __half* __restrict__ vkT, const __half* __restrict__ q,
                const float* __restrict__ zbuf, const __half* __restrict__ dw,
                const float* __restrict__ norm_w, __half* __restrict__ y)
{
    extern __shared__ char smc[];
    float* nw  = (float*)(smc + EPI_BYTES);
    float* ssq = nw + 256;
    float* rr  = ssq + 4 * 132;

    int b = blockIdx.z;
    int n0 = blockIdx.x * 128;
    const __half* Ab = vkT + (size_t)b * DIM * DIM;
    const __half* qg = q + (size_t)b * QKVD * NPOS + n0;
    const __half* dp = dw + (size_t)b * DIM * NPOS;
    __half* yp = y + (size_t)b * DIM * NPOS;

    int tid = threadIdx.x;
    int lane = tid & 31, wid = tid >> 5;
    int g = lane >> 2, tig = lane & 3;
    int warp_m = (wid & 3) * 64, warp_n = (wid >> 2) * 32;

    if (tid < 256) nw[tid] = norm_w[tid];

    uint32_t sbase;
    asm("{ .reg .u64 t; cvta.to.shared.u64 t, %1; cvt.u32.u64 %0, t; }" : "=r"(sbase) : "l"(smc));
    uint32_t sA = sbase, sB = sbase + 3 * AST2;

    int ac0 = tid, ac1 = tid + 512;
    int ar0 = ac0 >> 2, akc0 = ac0 & 3;
    int ar1 = ac1 >> 2, akc1 = ac1 & 3;
    uint32_t aoff0 = (uint32_t)(ar0 * 80 + akc0 * 16);
    uint32_t aoff1 = (uint32_t)(ar1 * 80 + akc1 * 16);
    int bkr = tid >> 4, bnc = tid & 15;
    uint32_t boff = (uint32_t)(bkr * 272 + bnc * 16);

    uint32_t aF = ldsmA_off(lane) + (uint32_t)warp_m * 80;
    uint32_t bFt = ldsmBt272_off(lane) + (uint32_t)warp_n * 2;

#pragma unroll
    for (int ps = 0; ps < 2; ++ps) {
        int kc = ps * 32;
        cp16(sA + ps * AST2 + aoff0, Ab + (size_t)ar0 * DIM + kc + akc0 * 8);
        cp16(sA + ps * AST2 + aoff1, Ab + (size_t)ar1 * DIM + kc + akc1 * 8);
        cp16(sB + ps * BSTT + boff, qg + (size_t)(kc + bkr) * NPOS + bnc * 8);
        CP_COMMIT();
    }

    float acc[4][4][4];
#pragma unroll
    for (int i = 0; i < 4; ++i)
#pragma unroll
        for (int j = 0; j < 4; ++j)
#pragma unroll
            for (int r = 0; r < 4; ++r) acc[i][j][r] = 0.f;

    const int S = 8;   // K=256, k32
    for (int s = 0; s < S; ++s) {
        CP_WAIT1();
        __syncthreads();
        if (s + 2 < S) {
            int buf2 = (s + 2) % 3;
            int kc = (s + 2) * 32;
            cp16(sA + buf2 * AST2 + aoff0, Ab + (size_t)ar0 * DIM + kc + akc0 * 8);
            cp16(sA + buf2 * AST2 + aoff1, Ab + (size_t)ar1 * DIM + kc + akc1 * 8);
            cp16(sB + buf2 * BSTT + boff, qg + (size_t)(kc + bkr) * NPOS + bnc * 8);
        }
        CP_COMMIT();
        uint32_t stA = sA + (s % 3) * AST2;
        uint32_t stB = sB + (s % 3) * BSTT;
#pragma unroll
        for (int h = 0; h < 2; ++h) {
            uint32_t af[4][4], bf[4][2];
#pragma unroll
            for (int i = 0; i < 4; ++i)
                ldsm_x4(af[i][0], af[i][1], af[i][2], af[i][3],
                        stA + aF + (uint32_t)(i * 16 * 80 + h * 32));
#pragma unroll
            for (int jj = 0; jj < 2; ++jj)
                ldsm_x4_t(bf[2 * jj][0], bf[2 * jj][1], bf[2 * jj + 1][0], bf[2 * jj + 1][1],
                          stB + bFt + (uint32_t)(jj * 32 + h * 16 * 272));
#pragma unroll
            for (int i = 0; i < 4; ++i)
#pragma unroll
                for (int j = 0; j < 4; ++j)
                    MMA_F16(acc[i][j], af[i][0], af[i][1], af[i][2], af[i][3], bf[j][0], bf[j][1]);
        }
    }

    // ---- fused epilogue ----
    float ss[8];
#pragma unroll
    for (int j = 0; j < 4; ++j) {
        int col = warp_n + j * 8 + tig * 2;
        float2 zv = *(const float2*)&zbuf[(size_t)b * NPOS + n0 + col];
        float iz0 = 1.f / zv.x, iz1 = 1.f / zv.y;
        float s0 = 0.f, s1 = 0.f;
#pragma unroll
        for (int i = 0; i < 4; ++i) {
            acc[i][j][0] *= iz0; acc[i][j][1] *= iz1;
            acc[i][j][2] *= iz0; acc[i][j][3] *= iz1;
            s0 += acc[i][j][0] * acc[i][j][0] + acc[i][j][2] * acc[i][j][2];
            s1 += acc[i][j][1] * acc[i][j][1] + acc[i][j][3] * acc[i][j][3];
        }
        ss[j * 2] = s0; ss[j * 2 + 1] = s1;
    }
#pragma unroll
    for (int o = 4; o <= 16; o <<= 1)
#pragma unroll
        for (int c = 0; c < 8; ++c) ss[c] += __shfl_xor_sync(0xFFFFFFFFu, ss[c], o);
    __syncthreads();
    if (g == 0) {
        int wm = wid & 3;
#pragma unroll
        for (int j = 0; j < 4; ++j) {
            int col = warp_n + j * 8 + tig * 2;
            ssq[wm * 132 + col] = ss[j * 2];
            ssq[wm * 132 + col + 1] = ss[j * 2 + 1];
        }
    }
    __syncthreads();
    if (tid < 128) {
        float s = ssq[tid] + ssq[132 + tid] + ssq[264 + tid] + ssq[396 + tid];
        rr[tid] = rsqrtf(s * (1.f / (float)DIM) + EPSF);
    }
    __syncthreads();
#pragma unroll
    for (int i = 0; i < 4; ++i) {
        int row0 = warp_m + i * 16 + g;
#pragma unroll
        for (int j = 0; j < 4; ++j) {
            int col = warp_n + j * 8 + tig * 2;
            float r0 = rr[col], r1 = rr[col + 1];
            float2 d0 = __half22float2(*(const __half2*)&dp[(size_t)row0 * NPOS + n0 + col]);
            float2 d1 = __half22float2(*(const __half2*)&dp[(size_t)(row0 + 8) * NPOS + n0 + col]);
            *(__half2*)&yp[(size_t)row0 * NPOS + n0 + col] =
                __floats2half2_rn(acc[i][j][0] * r0 * nw[row0] + d0.x,
                                  acc[i][j][1] * r1 * nw[row0] + d0.y);
            *(__half2*)&yp[(size_t)(row0 + 8) * NPOS + n0 + col] =
                __floats2half2_rn(acc[i][j][2] * r0 * nw[row0 + 8] + d1.x,
                                  acc[i][j][3] * r1 * nw[row0 + 8] + d1.y);
        }
    }
}

// ---------------- fp32 -> fp16 copy ----------------
__global__ void round_copy_h(const float* __restrict__ in, __half* __restrict__ out, int n)
{
    int i = blockIdx.x * 256 + threadIdx.x;
    if (i < n) out[i] = __float2half_rn(in[i]);
}

// ---------------- featmap in place on fp16 [d][n] slice ----------------
__global__ void featmap_kernel(__half* __restrict__ qkv)
{
    int b = blockIdx.z;
    __half* ptr = qkv + ((size_t)b * QKVD + (blockIdx.y ? 256 : 0)) * NPOS;
    int tx = threadIdx.x, ty = threadIdx.y;          // 32 x 8
    int n = blockIdx.x * 32 + tx;
    float t[32];
    float s = 0.f;
#pragma unroll
    for (int r = 0; r < 32; ++r) {
        float v = __half2float(ptr[(size_t)(ty * 32 + r) * NPOS + n]);
        v = fmaxf(v, 0.f) + EPSF;
        v = v * v;
        t[r] = v;
        s += v * v;
    }
    __shared__ float red[8][33];
    __shared__ float nrm[32];
    red[ty][tx] = s;
    __syncthreads();
    if (ty == 0) {
        float tot = 0.f;
#pragma unroll
        for (int k = 0; k < 8; ++k) tot += red[k][tx];
        nrm[tx] = 1.f / fmaxf(sqrtf(tot), 1e-12f);
    }
    __syncthreads();
    float inv = nrm[tx];
#pragma unroll
    for (int r = 0; r < 32; ++r)
        ptr[(size_t)(ty * 32 + r) * NPOS + n] = __float2half_rn(t[r] * inv);
}

// ---------------- kmean: warp per channel ----------------
__global__ void kmean_k(const __half* __restrict__ kbase, float* __restrict__ km)
{
    int b = blockIdx.y;
    int wid = threadIdx.x >> 5, lane = threadIdx.x & 31;
    int d = blockIdx.x * 8 + wid;
    const __half2* kp = (const __half2*)(kbase + (size_t)b * QKVD * NPOS + (size_t)d * NPOS);
    float s = 0.f;
#pragma unroll 8
    for (int i = lane; i < NPOS / 2; i += 32) {
        float2 v = __half22float2(kp[i]);
        s += v.x + v.y;
    }
#pragma unroll
    for (int o = 16; o > 0; o >>= 1) s += __shfl_xor_sync(0xFFFFFFFFu, s, o);
    if (lane == 0) km[b * DIM + d] = s * (1.f / (float)NPOS);
}

// ---------------- z[b][n] = kmean · q[:, n] + eps ----------------
__global__ void zcalc(const __half* __restrict__ q, const float* __restrict__ km, float* __restrict__ zo)
{
    __shared__ float kms[256];
    int b = blockIdx.y;
    int tid = threadIdx.x;
    kms[tid] = km[b * DIM + tid];
    __syncthreads();
    int n = blockIdx.x * 256 + tid;
    const __half* qp = q + (size_t)b * QKVD * NPOS + n;
    float s = 0.f;
#pragma unroll 4
    for (int d = 0; d < 256; ++d) s += kms[d] * __half2float(qp[(size_t)d * NPOS]);
    zo[(size_t)b * NPOS + n] = s + EPSF;
}

// ---------------- vkt reduce (8 chunks) + 1/N -> fp16 ----------------
__global__ void vkt_reduce(const float* __restrict__ part, __half* __restrict__ vkT)
{
    int idx = blockIdx.x * 256 + threadIdx.x;
    int b = idx >> 16, ij = idx & 65535;
    float s = 0.f;
#pragma unroll
    for (int c = 0; c < 8; ++c) s += part[(size_t)(b * 8 + c) * 65536 + ij];
    vkT[idx] = __float2half_rn(s * (1.f / (float)NPOS));
}

// ---------------- depthwise 5x5 on fp16 v slice -> fp16 dw ----------------
__global__ void dwconv_kernel(const __half* __restrict__ vbase, const float* __restrict__ w,
                              const float* __restrict__ bias, __half* __restrict__ dw)
{
    int ch = blockIdx.x, b = blockIdx.y;
    const __half* vp = vbase + (size_t)b * QKVD * NPOS + (size_t)ch * NPOS;
    __shared__ float sm[68][68];
    __shared__ float ws[25];
    int tid = threadIdx.x;
    if (tid < 25) ws[tid] = w[ch * 25 + tid];
    for (int idx = tid; idx < 68 * 68; idx += 256) {
        int r = idx / 68, c = idx % 68;
        int gr = r - 2, gc = c - 2;
        sm[r][c] = (gr >= 0 && gr < HH && gc >= 0 && gc < WW) ? __half2float(vp[gr * WW + gc]) : 0.f;
    }
    __syncthreads();
    float bv = bias[ch];
    for (int p = tid; p < NPOS; p += 256) {
        int py = p >> 6, px = p & 63;
        float acc = bv;
#pragma unroll
        for (int ky = 0; ky < 5; ++ky)
#pragma unroll
            for (int kx = 0; kx < 5; ++kx)
                acc += sm[py + ky][px + kx] * ws[ky * 5 + kx];
        dw[((size_t)b * DIM + ch) * NPOS + p] = __float2half_rn(acc);
    }
}

// ---------------- host ----------------
extern "C" void kernel_launch(void* const* d_in, const int* in_sizes, int n_in,
                              void* d_out, int out_size)
{
    const float* x      = (const float*)d_in[0];
    const float* qkv_w  = (const float*)d_in[1];
    const float* qkv_b  = (const float*)d_in[2];
    const float* dwc_w  = (const float*)d_in[3];
    const float* dwc_b  = (const float*)d_in[4];
    const float* norm_w = (const float*)d_in[5];
    const float* proj_w = (const float*)d_in[6];
    const float* proj_b = (const float*)d_in[7];
    float* out = (float*)d_out;

    __half *p_xh, *p_qkv, *p_vkT, *p_y, *p_qw, *p_pw, *p_dw;
    float *p_part, *p_z, *p_km;
    cudaGetSymbolAddress((void**)&p_xh, g_xh);
    cudaGetSymbolAddress((void**)&p_qkv, g_qkv);
    cudaGetSymbolAddress((void**)&p_vkT, g_vkT);
    cudaGetSymbolAddress((void**)&p_part, g_part);
    cudaGetSymbolAddress((void**)&p_dw, g_dw);
    cudaGetSymbolAddress((void**)&p_y, g_y);
    cudaGetSymbolAddress((void**)&p_z, g_z);
    cudaGetSymbolAddress((void**)&p_km, g_kmean);
    cudaGetSymbolAddress((void**)&p_qw, g_qw);
    cudaGetSymbolAddress((void**)&p_pw, g_pw);

    const size_t kOff = (size_t)256 * NPOS, vOff = (size_t)512 * NPOS;

    const int SMEM_G = 4 * ASTG + 4 * BSTG;                       // 122880
    const int SMEM_A = EPI_BYTES + (256 + 4 * 132 + 128) * 4;     // ~91 KB
    cudaFuncSetAttribute(hgemm, cudaFuncAttributeMaxDynamicSharedMemorySize, SMEM_G);
    cudaFuncSetAttribute(attn_fused, cudaFuncAttributeMaxDynamicSharedMemorySize, SMEM_A);

    // 1-3. convert x and weights to fp16
    round_copy_h<<<(BATCH * DIM * NPOS + 255) / 256, 256>>>(x, p_xh, BATCH * DIM * NPOS);
    round_copy_h<<<(QKVD * DIM + 255) / 256, 256>>>(qkv_w, p_qw, QKVD * DIM);
    round_copy_h<<<(DIM * DIM + 255) / 256, 256>>>(proj_w, p_pw, DIM * DIM);
    // 4. qkv[768][n] = qkv_w · x  (B trans), fp16 out, bias per-row
    hgemm<<<dim3(NPOS / 256, QKVD / 128, BATCH), 256, SMEM_G>>>(
        p_qw, p_xh, qkv_b, p_qkv, 256, DIM, NPOS, NPOS,
        0LL, (long long)DIM * NPOS, (long long)QKVD * NPOS, 1, 2, 1, 1);
    // 5. featmap q,k in place
    featmap_kernel<<<dim3(NPOS / 32, 2, BATCH), dim3(32, 8)>>>(p_qkv);
    // 6,7. kmean, z
    kmean_k<<<dim3(DIM / 8, BATCH), 256>>>(p_qkv + kOff, p_km);
    zcalc<<<dim3(NPOS / 256, BATCH), 256>>>(p_qkv, p_km, p_z);
    // 8,9. vkT = v · k^T / N  (split-K x8), fp32 partials -> fp16
    hgemm<<<dim3(DIM / 256, DIM / 128, BATCH * 8), 256, SMEM_G>>>(
        p_qkv + vOff, p_qkv + kOff, nullptr, p_part, 512, NPOS, NPOS, DIM,
        (long long)QKVD * NPOS, (long long)QKVD * NPOS, (long long)DIM * DIM, 8, 0, 0, 0);
    vkt_reduce<<<dim3(BATCH * DIM * DIM / 256), 256>>>(p_part, p_vkT);
    // 10. depthwise conv on v -> fp16 dw
    dwconv_kernel<<<dim3(DIM, BATCH), 256>>>(p_qkv + vOff, dwc_w, dwc_b, p_dw);
    // 11. fused attn -> y[d][n] fp16
    attn_fused<<<dim3(NPOS / 128, 1, BATCH), 512, SMEM_A>>>(p_vkT, p_qkv, p_z, p_dw, norm_w, p_y);
    // 12. out[c][n] = proj_w · y + proj_b  (B trans), fp32 out
    hgemm<<<dim3(NPOS / 256, DIM / 128, BATCH), 256, SMEM_G>>>(
        p_pw, p_y, proj_b, out, 256, DIM, NPOS, NPOS,
        0LL, (long long)DIM * NPOS, (long long)DIM * NPOS, 1, 2, 1, 0);
}